// round 7
// baseline (speedup 1.0000x reference)
#include <cuda_runtime.h>
#include <cuda_fp16.h>
#include <math.h>
#include <stdint.h>

#define N_NODES 4096
#define IN_F    512
#define NHEAD   8
#define DHEAD   64
#define CTOT    512
#define NB_CAP  128

// Scratch (static device globals — no runtime allocation)
__device__ __half g_mxh[N_NODES * CTOT];       // x @ W in fp16 (4 MB)
__device__ float  g_wt [CTOT * IN_F];          // W^T K-major tf32 (1 MB)
__device__ float  g_wexp[N_NODES * NHEAD];     // exp weights (128 KB)
__device__ unsigned short g_nbr[N_NODES][NB_CAP]; // CSR neighbor lists (1 MB)
__device__ int    g_ncnt[N_NODES];

// ---------------- helpers ----------------
__device__ __forceinline__ uint32_t smem_u32(const void* p) {
    return (uint32_t)__cvta_generic_to_shared(p);
}
__device__ __forceinline__ void cpa16(uint32_t saddr, const float* g) {
    asm volatile("cp.async.cg.shared.global [%0], [%1], 16;\n" :: "r"(saddr), "l"(g));
}
__device__ __forceinline__ float tf32r(float v) {
    uint32_t r;
    asm("cvt.rna.tf32.f32 %0, %1;" : "=r"(r) : "f"(v));
    return __uint_as_float(r);
}
__device__ __forceinline__ void mma_tf32(float* c, const uint32_t* a, const uint32_t* b) {
    asm volatile(
        "mma.sync.aligned.m16n8k8.row.col.f32.tf32.tf32.f32 "
        "{%0,%1,%2,%3}, {%4,%5,%6,%7}, {%8,%9}, {%0,%1,%2,%3};"
        : "+f"(c[0]), "+f"(c[1]), "+f"(c[2]), "+f"(c[3])
        : "r"(a[0]), "r"(a[1]), "r"(a[2]), "r"(a[3]), "r"(b[0]), "r"(b[1]));
}
__device__ __forceinline__ void ffma2(unsigned long long& d,
                                      unsigned long long a,
                                      unsigned long long b) {
    asm("fma.rn.f32x2 %0, %1, %2, %0;" : "+l"(d) : "l"(a), "l"(b));
}
__device__ __forceinline__ unsigned long long pack_dup(float x) {
    unsigned long long r;
    unsigned u = __float_as_uint(x);
    asm("mov.b64 %0, {%1, %1};" : "=l"(r) : "r"(u));
    return r;
}
__device__ __forceinline__ unsigned long long packf2(float2 f) {
    unsigned long long r;
    asm("mov.b64 %0, {%1, %2};" : "=l"(r)
        : "r"(__float_as_uint(f.x)), "r"(__float_as_uint(f.y)));
    return r;
}
__device__ __forceinline__ float2 unpack2(unsigned long long v) {
    unsigned lo, hi;
    asm("mov.b64 {%0, %1}, %2;" : "=r"(lo), "=r"(hi) : "l"(v));
    return make_float2(__uint_as_float(lo), __uint_as_float(hi));
}

// ---------------------------------------------------------------------------
// Prep: g_wt[c][f] = round_tf32(W[c>>6][f][c&63])
// ---------------------------------------------------------------------------
__global__ __launch_bounds__(256) void prep_kernel(const float* __restrict__ W)
{
    __shared__ float t[64][65];
    const int h  = blockIdx.x >> 3;
    const int f0 = (blockIdx.x & 7) * 64;
    const float* Wb = W + (size_t)h * IN_F * DHEAD + (size_t)f0 * DHEAD;
    for (int e = threadIdx.x; e < 4096; e += 256) {
        int i = e >> 6, d = e & 63;
        t[i][d] = Wb[i * 64 + d];
    }
    __syncthreads();
    for (int e = threadIdx.x; e < 4096; e += 256) {
        int d = e >> 6, i = e & 63;
        g_wt[(size_t)(h * 64 + d) * IN_F + f0 + i] = tf32r(t[i][d]);
    }
}

// ---------------------------------------------------------------------------
// Merged kernel: blocks [0,128) = tf32 GEMM tiles (compute-bound),
//                blocks [128,128+4096) = adjacency compaction (DRAM-bound).
// Complementary pipes -> the 64MB adj stream hides behind the GEMM.
// ---------------------------------------------------------------------------
#define KT 16
#define NKT (IN_F / KT)   // 32
#define CSEG_CAP 28

__global__ __launch_bounds__(256) void gemm_compact_kernel(
    const float* __restrict__ x, const float* __restrict__ adj)
{
    __shared__ float As[2][128][20];
    __shared__ float Bs[2][128][20];
    __shared__ unsigned short cseg[8][CSEG_CAP];
    __shared__ int ccnt[8], coffs[8];

    const int tid  = threadIdx.x;

    if (blockIdx.x >= 128) {
        // ================= compaction branch: one row per block =================
        const int i    = blockIdx.x - 128;
        const int warp = tid >> 5;
        const int lane = tid & 31;
        const float* arow = adj + (size_t)i * N_NODES + warp * 512;

        float4 v[4];
        #pragma unroll
        for (int p = 0; p < 4; p++)
            v[p] = __ldg((const float4*)(arow + p * 128 + lane * 4));

        int cnt = 0;
        #pragma unroll
        for (int p = 0; p < 4; p++) {
            unsigned m4 = (v[p].x > 0.f ? 1u : 0u) | (v[p].y > 0.f ? 2u : 0u)
                        | (v[p].z > 0.f ? 4u : 0u) | (v[p].w > 0.f ? 8u : 0u);
            int c = __popc(m4), inc = c;
            #pragma unroll
            for (int d2 = 1; d2 < 32; d2 <<= 1) {
                int t = __shfl_up_sync(0xFFFFFFFFu, inc, d2);
                if (lane >= d2) inc += t;
            }
            int pos = cnt + inc - c;
            int base = warp * 512 + p * 128 + lane * 4;
            #pragma unroll
            for (int b = 0; b < 4; b++)
                if ((m4 >> b) & 1u) cseg[warp][pos++] = (unsigned short)(base + b);
            cnt += __shfl_sync(0xFFFFFFFFu, inc, 31);
        }
        if (lane == 0) ccnt[warp] = cnt;
        __syncthreads();
        if (tid == 0) {
            int s = 0;
            #pragma unroll
            for (int w = 0; w < 8; w++) { coffs[w] = s; s += ccnt[w]; }
            g_ncnt[i] = s;
        }
        __syncthreads();
        {
            const int o = coffs[warp], cw = ccnt[warp];
            for (int k = lane; k < cw; k += 32) g_nbr[i][o + k] = cseg[warp][k];
        }
        return;
    }

    // ================= GEMM branch =================
    const int wid  = tid >> 5, lane = tid & 31;
    const int wm   = wid >> 2, wn = wid & 3;
    const int g    = lane >> 2, t4 = lane & 3;
    const int m0   = (blockIdx.x & 31) * 128;
    const int c0   = (blockIdx.x >> 5) * 128;

    const uint32_t as_b = smem_u32(&As[0][0][0]);
    const uint32_t bs_b = smem_u32(&Bs[0][0][0]);

    float acc[4][4][4];
    #pragma unroll
    for (int mt = 0; mt < 4; mt++)
        #pragma unroll
        for (int nt = 0; nt < 4; nt++)
            #pragma unroll
            for (int q = 0; q < 4; q++) acc[mt][nt][q] = 0.f;

    const float* arow = x    + (size_t)m0 * IN_F;
    const float* brow = g_wt + (size_t)c0 * IN_F;

    auto fill = [&](int s, int t) {
        const int f0 = t * KT;
        #pragma unroll
        for (int l = 0; l < 2; l++) {
            int idx = tid + l * 256;
            int row = idx >> 2, kc = (idx & 3) * 4;
            uint32_t off = (uint32_t)(((s * 128 + row) * 20 + kc) * 4);
            cpa16(as_b + off, arow + (size_t)row * IN_F + f0 + kc);
            cpa16(bs_b + off, brow + (size_t)row * IN_F + f0 + kc);
        }
    };

    fill(0, 0);
    asm volatile("cp.async.commit_group;" ::: "memory");

    for (int t = 0; t < NKT; t++) {
        const int s = t & 1;
        if (t + 1 < NKT) {
            fill(s ^ 1, t + 1);
            asm volatile("cp.async.commit_group;" ::: "memory");
            asm volatile("cp.async.wait_group 1;" ::: "memory");
        } else {
            asm volatile("cp.async.wait_group 0;" ::: "memory");
        }
        __syncthreads();

        #pragma unroll
        for (int ks = 0; ks < 2; ks++) {
            const int kb = ks * 8;
            uint32_t af[4][4];
            #pragma unroll
            for (int mt = 0; mt < 4; mt++) {
                int m = wm * 64 + mt * 16 + g;
                af[mt][0] = __float_as_uint(As[s][m    ][kb + t4]);
                af[mt][1] = __float_as_uint(As[s][m + 8][kb + t4]);
                af[mt][2] = __float_as_uint(As[s][m    ][kb + t4 + 4]);
                af[mt][3] = __float_as_uint(As[s][m + 8][kb + t4 + 4]);
            }
            uint32_t bf[4][2];
            #pragma unroll
            for (int nt = 0; nt < 4; nt++) {
                int n = wn * 32 + nt * 8 + g;
                bf[nt][0] = __float_as_uint(Bs[s][n][kb + t4]);
                bf[nt][1] = __float_as_uint(Bs[s][n][kb + t4 + 4]);
            }
            #pragma unroll
            for (int mt = 0; mt < 4; mt++)
                #pragma unroll
                for (int nt = 0; nt < 4; nt++)
                    mma_tf32(acc[mt][nt], af[mt], bf[nt]);
        }
        __syncthreads();
    }

    #pragma unroll
    for (int mt = 0; mt < 4; mt++) {
        #pragma unroll
        for (int nt = 0; nt < 4; nt++) {
            int row = m0 + wm * 64 + mt * 16 + g;
            int col = c0 + wn * 32 + nt * 8 + t4 * 2;
            *(__half2*)(g_mxh + (size_t)row * CTOT + col) =
                __floats2half2_rn(acc[mt][nt][0], acc[mt][nt][1]);
            *(__half2*)(g_mxh + (size_t)(row + 8) * CTOT + col) =
                __floats2half2_rn(acc[mt][nt][2], acc[mt][nt][3]);
        }
    }
}

// ---------------------------------------------------------------------------
// Kernel 2: g_wexp[n,h] = exp(mx[n,h,:] . a_dst[h,:])
// (a_origin source term cancels in the row softmax)
// ---------------------------------------------------------------------------
__global__ __launch_bounds__(256) void wexp_kernel(const float* __restrict__ a_dst)
{
    const int gw   = blockIdx.x * 8 + (threadIdx.x >> 5);
    const int lane = threadIdx.x & 31;
    const int n    = gw >> 2;
    const int hp   = gw & 3;
    const int head = 2 * hp + (lane >> 4);

    uint2 raw = __ldg((const uint2*)(g_mxh + (size_t)n * CTOT + hp * 128 + lane * 4));
    float2 v0 = __half22float2(*(__half2*)&raw.x);
    float2 v1 = __half22float2(*(__half2*)&raw.y);
    float4 a  = __ldg((const float4*)(a_dst + head * DHEAD + (lane & 15) * 4));
    float t = v0.x * a.x + v0.y * a.y + v1.x * a.z + v1.y * a.w;
    #pragma unroll
    for (int o = 8; o > 0; o >>= 1) t += __shfl_xor_sync(0xFFFFFFFFu, t, o);
    if ((lane & 15) == 0) g_wexp[n * NHEAD + head] = expf(t);
}

// ---------------------------------------------------------------------------
// Kernel 3 (gather): out[i,c] = sum_j w[j,h] mx[j,c] / sum_j w[j,h]
// Reads the CSR built by the merged kernel. 128 thr/block, one block per row.
// 64 channel-groups (8 halves) x 2 neighbor sub-streams, f32x2 accumulation.
// ---------------------------------------------------------------------------
__device__ __forceinline__ void accp(unsigned long long* a2, uint4 r,
                                     unsigned long long wp) {
    ffma2(a2[0], packf2(__half22float2(*(__half2*)&r.x)), wp);
    ffma2(a2[1], packf2(__half22float2(*(__half2*)&r.y)), wp);
    ffma2(a2[2], packf2(__half22float2(*(__half2*)&r.z)), wp);
    ffma2(a2[3], packf2(__half22float2(*(__half2*)&r.w)), wp);
}

__global__ __launch_bounds__(128) void gather_kernel(float* __restrict__ out)
{
    __shared__ unsigned short ulist[NB_CAP];
    __shared__ float wsh[NB_CAP][NHEAD];
    __shared__ float pac[64][9];
    __shared__ float pden1[64];

    const int i   = blockIdx.x;
    const int tid = threadIdx.x;
    const int nb  = __ldg(g_ncnt + i);

    if (tid < nb) ulist[tid] = g_nbr[i][tid];
    __syncthreads();
    for (int idx = tid; idx < nb * NHEAD; idx += 128) {
        int k = idx >> 3, h2 = idx & 7;
        wsh[k][h2] = __ldg(g_wexp + (int)ulist[k] * NHEAD + h2);
    }
    __syncthreads();

    const int cg  = tid & 63;            // channels [cg*8, cg*8+8)
    const int sub = tid >> 6;            // neighbors k === sub (mod 2)
    const int h   = cg >> 3;
    const __half* base = g_mxh + cg * 8;

    unsigned long long acc2[4] = {0ull, 0ull, 0ull, 0ull};
    float den = 0.f;
    int k = sub;
    for (; k + 6 < nb; k += 8) {
        int j0 = ulist[k], j1 = ulist[k + 2], j2 = ulist[k + 4], j3 = ulist[k + 6];
        uint4 r0 = __ldg((const uint4*)(base + (size_t)j0 * CTOT));
        uint4 r1 = __ldg((const uint4*)(base + (size_t)j1 * CTOT));
        uint4 r2 = __ldg((const uint4*)(base + (size_t)j2 * CTOT));
        uint4 r3 = __ldg((const uint4*)(base + (size_t)j3 * CTOT));
        float w0 = wsh[k][h], w1 = wsh[k + 2][h], w2 = wsh[k + 4][h], w3 = wsh[k + 6][h];
        accp(acc2, r0, pack_dup(w0));
        accp(acc2, r1, pack_dup(w1));
        accp(acc2, r2, pack_dup(w2));
        accp(acc2, r3, pack_dup(w3));
        den += w0; den += w1; den += w2; den += w3;
    }
    for (; k < nb; k += 2) {
        int j0 = ulist[k];
        uint4 r0 = __ldg((const uint4*)(base + (size_t)j0 * CTOT));
        float w0 = wsh[k][h];
        accp(acc2, r0, pack_dup(w0));
        den += w0;
    }

    float accf[8];
    #pragma unroll
    for (int q = 0; q < 4; q++) {
        float2 f = unpack2(acc2[q]);
        accf[2 * q] = f.x; accf[2 * q + 1] = f.y;
    }

    if (sub == 1) {
        #pragma unroll
        for (int q = 0; q < 8; q++) pac[cg][q] = accf[q];
        pden1[cg] = den;
    }
    __syncthreads();
    if (sub == 0) {
        den += pden1[cg];
        float inv = 1.f / den;
        float* op = out + (size_t)i * CTOT + cg * 8;
        *(float4*)(op) = make_float4((accf[0] + pac[cg][0]) * inv,
                                     (accf[1] + pac[cg][1]) * inv,
                                     (accf[2] + pac[cg][2]) * inv,
                                     (accf[3] + pac[cg][3]) * inv);
        *(float4*)(op + 4) = make_float4((accf[4] + pac[cg][4]) * inv,
                                         (accf[5] + pac[cg][5]) * inv,
                                         (accf[6] + pac[cg][6]) * inv,
                                         (accf[7] + pac[cg][7]) * inv);
    }
}

// ---------------------------------------------------------------------------
// Inputs: x[4096,512], adj[4096,4096], W[8,512,64], a_origin[8,64] (cancels),
//         a_dst[8,64].  Output: float32 [4096, 512]
// ---------------------------------------------------------------------------
extern "C" void kernel_launch(void* const* d_in, const int* in_sizes, int n_in,
                              void* d_out, int out_size)
{
    const float* x     = (const float*)d_in[0];
    const float* adj   = (const float*)d_in[1];
    const float* W     = (const float*)d_in[2];
    const float* a_dst = (const float*)d_in[4];
    float* out = (float*)d_out;

    prep_kernel<<<64, 256>>>(W);
    gemm_compact_kernel<<<128 + N_NODES, 256>>>(x, adj);
    wexp_kernel<<<2048, 256>>>(a_dst);
    gather_kernel<<<N_NODES, 128>>>(out);
}

// round 8
// speedup vs baseline: 1.0842x; 1.0842x over previous
#include <cuda_runtime.h>
#include <cuda_fp16.h>
#include <math.h>
#include <stdint.h>

#define N_NODES 4096
#define IN_F    512
#define NHEAD   8
#define DHEAD   64
#define CTOT    512
#define NB_CAP  128

// Scratch (static device globals — no runtime allocation)
__device__ __half g_mxh[N_NODES * CTOT];   // x @ W in fp16 (4 MB, L2-resident)
__device__ float  g_wt [CTOT * IN_F];      // W^T K-major tf32 (1 MB)
__device__ float  g_wexp[N_NODES * NHEAD]; // exp weights (128 KB)

// ---------------- helpers ----------------
__device__ __forceinline__ uint32_t smem_u32(const void* p) {
    return (uint32_t)__cvta_generic_to_shared(p);
}
__device__ __forceinline__ void cpa16(uint32_t saddr, const float* g) {
    asm volatile("cp.async.cg.shared.global [%0], [%1], 16;\n" :: "r"(saddr), "l"(g));
}
__device__ __forceinline__ float tf32r(float v) {
    uint32_t r;
    asm("cvt.rna.tf32.f32 %0, %1;" : "=r"(r) : "f"(v));
    return __uint_as_float(r);
}
__device__ __forceinline__ void mma_tf32(float* c, const uint32_t* a, const uint32_t* b) {
    asm volatile(
        "mma.sync.aligned.m16n8k8.row.col.f32.tf32.tf32.f32 "
        "{%0,%1,%2,%3}, {%4,%5,%6,%7}, {%8,%9}, {%0,%1,%2,%3};"
        : "+f"(c[0]), "+f"(c[1]), "+f"(c[2]), "+f"(c[3])
        : "r"(a[0]), "r"(a[1]), "r"(a[2]), "r"(a[3]), "r"(b[0]), "r"(b[1]));
}
__device__ __forceinline__ void ffma2(unsigned long long& d,
                                      unsigned long long a,
                                      unsigned long long b) {
    asm("fma.rn.f32x2 %0, %1, %2, %0;" : "+l"(d) : "l"(a), "l"(b));
}
__device__ __forceinline__ unsigned long long pack_dup(float x) {
    unsigned long long r;
    unsigned u = __float_as_uint(x);
    asm("mov.b64 %0, {%1, %1};" : "=l"(r) : "r"(u));
    return r;
}
__device__ __forceinline__ unsigned long long packf2(float2 f) {
    unsigned long long r;
    asm("mov.b64 %0, {%1, %2};" : "=l"(r)
        : "r"(__float_as_uint(f.x)), "r"(__float_as_uint(f.y)));
    return r;
}
__device__ __forceinline__ float2 unpack2(unsigned long long v) {
    unsigned lo, hi;
    asm("mov.b64 {%0, %1}, %2;" : "=r"(lo), "=r"(hi) : "l"(v));
    return make_float2(__uint_as_float(lo), __uint_as_float(hi));
}

// ---------------------------------------------------------------------------
// Prep: g_wt[c][f] = round_tf32(W[c>>6][f][c&63])
// ---------------------------------------------------------------------------
__global__ __launch_bounds__(256) void prep_kernel(const float* __restrict__ W)
{
    __shared__ float t[64][65];
    const int h  = blockIdx.x >> 3;
    const int f0 = (blockIdx.x & 7) * 64;
    const float* Wb = W + (size_t)h * IN_F * DHEAD + (size_t)f0 * DHEAD;
    for (int e = threadIdx.x; e < 4096; e += 256) {
        int i = e >> 6, d = e & 63;
        t[i][d] = Wb[i * 64 + d];
    }
    __syncthreads();
    for (int e = threadIdx.x; e < 4096; e += 256) {
        int d = e >> 6, i = e & 63;
        g_wt[(size_t)(h * 64 + d) * IN_F + f0 + i] = tf32r(t[i][d]);
    }
}

// ---------------------------------------------------------------------------
// Kernel 1: mx = x @ wt^T via mma.sync m16n8k8 tf32.
// 128x128 CTA tile, 512 threads (16 warps, 4x4 grid, 32x32 warp tiles)
// -> 4 warps/SMSP for LDS->HMMA latency overlap.
// ---------------------------------------------------------------------------
#define KT 16
#define NKT (IN_F / KT)   // 32

__global__ __launch_bounds__(512) void gemm_mx_kernel(const float* __restrict__ x)
{
    __shared__ float As[2][128][20];
    __shared__ float Bs[2][128][20];

    const int tid  = threadIdx.x;
    const int wid  = tid >> 5, lane = tid & 31;
    const int wm   = wid >> 2, wn = wid & 3;        // 4 x 4 warp grid
    const int g    = lane >> 2, t4 = lane & 3;
    const int m0   = blockIdx.x * 128;
    const int c0   = blockIdx.y * 128;

    const uint32_t as_b = smem_u32(&As[0][0][0]);
    const uint32_t bs_b = smem_u32(&Bs[0][0][0]);

    float acc[2][4][4];
    #pragma unroll
    for (int mt = 0; mt < 2; mt++)
        #pragma unroll
        for (int nt = 0; nt < 4; nt++)
            #pragma unroll
            for (int q = 0; q < 4; q++) acc[mt][nt][q] = 0.f;

    const float* arow = x    + (size_t)m0 * IN_F;
    const float* brow = g_wt + (size_t)c0 * IN_F;

    auto fill = [&](int s, int t) {
        const int f0 = t * KT;
        int row = tid >> 2, kc = (tid & 3) * 4;
        uint32_t off = (uint32_t)(((s * 128 + row) * 20 + kc) * 4);
        cpa16(as_b + off, arow + (size_t)row * IN_F + f0 + kc);
        cpa16(bs_b + off, brow + (size_t)row * IN_F + f0 + kc);
    };

    fill(0, 0);
    asm volatile("cp.async.commit_group;" ::: "memory");

    for (int t = 0; t < NKT; t++) {
        const int s = t & 1;
        if (t + 1 < NKT) {
            fill(s ^ 1, t + 1);
            asm volatile("cp.async.commit_group;" ::: "memory");
            asm volatile("cp.async.wait_group 1;" ::: "memory");
        } else {
            asm volatile("cp.async.wait_group 0;" ::: "memory");
        }
        __syncthreads();

        #pragma unroll
        for (int ks = 0; ks < 2; ks++) {
            const int kb = ks * 8;
            uint32_t af[2][4];
            #pragma unroll
            for (int mt = 0; mt < 2; mt++) {
                int m = wm * 32 + mt * 16 + g;
                af[mt][0] = __float_as_uint(As[s][m    ][kb + t4]);
                af[mt][1] = __float_as_uint(As[s][m + 8][kb + t4]);
                af[mt][2] = __float_as_uint(As[s][m    ][kb + t4 + 4]);
                af[mt][3] = __float_as_uint(As[s][m + 8][kb + t4 + 4]);
            }
            uint32_t bf[4][2];
            #pragma unroll
            for (int nt = 0; nt < 4; nt++) {
                int n = wn * 32 + nt * 8 + g;
                bf[nt][0] = __float_as_uint(Bs[s][n][kb + t4]);
                bf[nt][1] = __float_as_uint(Bs[s][n][kb + t4 + 4]);
            }
            #pragma unroll
            for (int mt = 0; mt < 2; mt++)
                #pragma unroll
                for (int nt = 0; nt < 4; nt++)
                    mma_tf32(acc[mt][nt], af[mt], bf[nt]);
        }
        __syncthreads();
    }

    // epilogue: write fp16
    #pragma unroll
    for (int mt = 0; mt < 2; mt++) {
        #pragma unroll
        for (int nt = 0; nt < 4; nt++) {
            int row = m0 + wm * 32 + mt * 16 + g;
            int col = c0 + wn * 32 + nt * 8 + t4 * 2;
            *(__half2*)(g_mxh + (size_t)row * CTOT + col) =
                __floats2half2_rn(acc[mt][nt][0], acc[mt][nt][1]);
            *(__half2*)(g_mxh + (size_t)(row + 8) * CTOT + col) =
                __floats2half2_rn(acc[mt][nt][2], acc[mt][nt][3]);
        }
    }
}

// ---------------------------------------------------------------------------
// Kernel 2: g_wexp[n,h] = exp(mx[n,h,:] . a_dst[h,:])
// (a_origin source term cancels in the row softmax)
// ---------------------------------------------------------------------------
__global__ __launch_bounds__(256) void wexp_kernel(const float* __restrict__ a_dst)
{
    const int gw   = blockIdx.x * 8 + (threadIdx.x >> 5);
    const int lane = threadIdx.x & 31;
    const int n    = gw >> 2;
    const int hp   = gw & 3;
    const int head = 2 * hp + (lane >> 4);

    uint2 raw = __ldg((const uint2*)(g_mxh + (size_t)n * CTOT + hp * 128 + lane * 4));
    float2 v0 = __half22float2(*(__half2*)&raw.x);
    float2 v1 = __half22float2(*(__half2*)&raw.y);
    float4 a  = __ldg((const float4*)(a_dst + head * DHEAD + (lane & 15) * 4));
    float t = v0.x * a.x + v0.y * a.y + v1.x * a.z + v1.y * a.w;
    #pragma unroll
    for (int o = 8; o > 0; o >>= 1) t += __shfl_xor_sync(0xFFFFFFFFu, t, o);
    if ((lane & 15) == 0) g_wexp[n * NHEAD + head] = expf(t);
}

// ---------------------------------------------------------------------------
// Kernel 3: out[i,c] = sum_{j in adj(i)} w[j,h] mx[j,c] / sum_j w[j,h]
// One block (128 thr) per row; Phase A adj compaction (DRAM) overlaps with
// Phase B gathers (L2) across resident blocks.
// Phase A: prefetch all 8 float4 per lane, then ordered ballot-scan compact.
// Phase B: 64 channel-groups x 2 neighbor sub-streams, f32x2 accumulation.
// ---------------------------------------------------------------------------
#define SEG_CAP 96

__device__ __forceinline__ void accp(unsigned long long* a2, uint4 r,
                                     unsigned long long wp) {
    ffma2(a2[0], packf2(__half22float2(*(__half2*)&r.x)), wp);
    ffma2(a2[1], packf2(__half22float2(*(__half2*)&r.y)), wp);
    ffma2(a2[2], packf2(__half22float2(*(__half2*)&r.z)), wp);
    ffma2(a2[3], packf2(__half22float2(*(__half2*)&r.w)), wp);
}

__global__ __launch_bounds__(128) void aggregate_kernel(
    const float* __restrict__ adj, float* __restrict__ out)
{
    __shared__ unsigned short seg[4][SEG_CAP];
    __shared__ int cnts[4], nb_sh;
    __shared__ int offs[4];
    __shared__ unsigned short ulist[NB_CAP];
    __shared__ float wsh[NB_CAP][NHEAD];
    __shared__ float pac[64][9];
    __shared__ float pden1[64];

    const int i    = blockIdx.x;
    const int tid  = threadIdx.x;
    const int warp = tid >> 5;
    const int lane = tid & 31;

    // ---- Phase A: prefetch 8 x float4, then ordered compaction ----
    {
        const float* arow = adj + (size_t)i * N_NODES + warp * 1024;
        float4 v[8];
        #pragma unroll
        for (int p = 0; p < 8; p++)
            v[p] = __ldg((const float4*)(arow + p * 128 + lane * 4));

        int cnt = 0;
        #pragma unroll
        for (int p = 0; p < 8; p++) {
            unsigned m4 = (v[p].x > 0.f ? 1u : 0u) | (v[p].y > 0.f ? 2u : 0u)
                        | (v[p].z > 0.f ? 4u : 0u) | (v[p].w > 0.f ? 8u : 0u);
            int c = __popc(m4), inc = c;
            #pragma unroll
            for (int d2 = 1; d2 < 32; d2 <<= 1) {
                int t = __shfl_up_sync(0xFFFFFFFFu, inc, d2);
                if (lane >= d2) inc += t;
            }
            int pos = cnt + inc - c;
            int base = warp * 1024 + p * 128 + lane * 4;
            #pragma unroll
            for (int b = 0; b < 4; b++)
                if ((m4 >> b) & 1u) seg[warp][pos++] = (unsigned short)(base + b);
            cnt += __shfl_sync(0xFFFFFFFFu, inc, 31);
        }
        if (lane == 0) cnts[warp] = cnt;
    }
    __syncthreads();
    if (tid == 0) {
        int s = 0;
        #pragma unroll
        for (int w = 0; w < 4; w++) { offs[w] = s; s += cnts[w]; }
        nb_sh = s;
    }
    __syncthreads();
    {
        const int o = offs[warp], cw = cnts[warp];
        for (int k = lane; k < cw; k += 32) ulist[o + k] = seg[warp][k];
        for (int idx = lane; idx < cw * NHEAD; idx += 32) {
            int k = idx >> 3, h2 = idx & 7;
            wsh[o + k][h2] = __ldg(g_wexp + (int)seg[warp][k] * NHEAD + h2);
        }
    }
    __syncthreads();

    // ---- Phase B ----
    const int nb  = nb_sh;
    const int cg  = tid & 63;            // channels [cg*8, cg*8+8)
    const int sub = tid >> 6;            // neighbors k === sub (mod 2)
    const int h   = cg >> 3;
    const __half* base = g_mxh + cg * 8;

    unsigned long long acc2[4] = {0ull, 0ull, 0ull, 0ull};
    float den = 0.f;
    int k = sub;
    for (; k + 6 < nb; k += 8) {
        int j0 = ulist[k], j1 = ulist[k + 2], j2 = ulist[k + 4], j3 = ulist[k + 6];
        uint4 r0 = __ldg((const uint4*)(base + (size_t)j0 * CTOT));
        uint4 r1 = __ldg((const uint4*)(base + (size_t)j1 * CTOT));
        uint4 r2 = __ldg((const uint4*)(base + (size_t)j2 * CTOT));
        uint4 r3 = __ldg((const uint4*)(base + (size_t)j3 * CTOT));
        float w0 = wsh[k][h], w1 = wsh[k + 2][h], w2 = wsh[k + 4][h], w3 = wsh[k + 6][h];
        accp(acc2, r0, pack_dup(w0));
        accp(acc2, r1, pack_dup(w1));
        accp(acc2, r2, pack_dup(w2));
        accp(acc2, r3, pack_dup(w3));
        den += w0; den += w1; den += w2; den += w3;
    }
    for (; k < nb; k += 2) {
        int j0 = ulist[k];
        uint4 r0 = __ldg((const uint4*)(base + (size_t)j0 * CTOT));
        float w0 = wsh[k][h];
        accp(acc2, r0, pack_dup(w0));
        den += w0;
    }

    float accf[8];
    #pragma unroll
    for (int q = 0; q < 4; q++) {
        float2 f = unpack2(acc2[q]);
        accf[2 * q] = f.x; accf[2 * q + 1] = f.y;
    }

    if (sub == 1) {
        #pragma unroll
        for (int q = 0; q < 8; q++) pac[cg][q] = accf[q];
        pden1[cg] = den;
    }
    __syncthreads();
    if (sub == 0) {
        den += pden1[cg];
        float inv = 1.f / den;
        float* op = out + (size_t)i * CTOT + cg * 8;
        *(float4*)(op) = make_float4((accf[0] + pac[cg][0]) * inv,
                                     (accf[1] + pac[cg][1]) * inv,
                                     (accf[2] + pac[cg][2]) * inv,
                                     (accf[3] + pac[cg][3]) * inv);
        *(float4*)(op + 4) = make_float4((accf[4] + pac[cg][4]) * inv,
                                         (accf[5] + pac[cg][5]) * inv,
                                         (accf[6] + pac[cg][6]) * inv,
                                         (accf[7] + pac[cg][7]) * inv);
    }
}

// ---------------------------------------------------------------------------
// Inputs: x[4096,512], adj[4096,4096], W[8,512,64], a_origin[8,64] (cancels),
//         a_dst[8,64].  Output: float32 [4096, 512]
// ---------------------------------------------------------------------------
extern "C" void kernel_launch(void* const* d_in, const int* in_sizes, int n_in,
                              void* d_out, int out_size)
{
    const float* x     = (const float*)d_in[0];
    const float* adj   = (const float*)d_in[1];
    const float* W     = (const float*)d_in[2];
    const float* a_dst = (const float*)d_in[4];
    float* out = (float*)d_out;

    prep_kernel<<<64, 256>>>(W);
    gemm_mx_kernel<<<dim3(32, 4), 512>>>(x);
    wexp_kernel<<<2048, 256>>>(a_dst);
    aggregate_kernel<<<N_NODES, 128>>>(adj, out);
}